// round 11
// baseline (speedup 1.0000x reference)
#include <cuda_runtime.h>
#include <math.h>
#include <stdint.h>

// Problem constants
#define D_   1024
#define H_   16
#define DK_  64
#define B_   8
#define SQ_  512
#define SK_  1024
#define FF_  4096
#define ROWS_Q (B_*SQ_)   // 4096
#define ROWS_K (B_*SK_)   // 8192

// ---------------------------------------------------------------------------
// Static device scratch (no allocations allowed in kernel_launch)
// ---------------------------------------------------------------------------
__device__ float g_q  [(size_t)ROWS_Q * D_];          // 16 MB
__device__ float g_k  [(size_t)ROWS_K * D_];          // 32 MB
__device__ float g_v  [(size_t)ROWS_K * D_];          // 32 MB
__device__ float g_ctx[(size_t)ROWS_Q * D_];          // 16 MB
__device__ float g_o  [(size_t)ROWS_Q * D_];          // 16 MB
__device__ float g_x1 [(size_t)ROWS_Q * D_];          // 16 MB
__device__ float g_s  [(size_t)B_*H_*SQ_*SQ_];        // 134 MB (self-attn scores)
__device__ float g_h  [(size_t)ROWS_Q * FF_];         // 67 MB (FFN hidden)

// ---------------------------------------------------------------------------
// SGEMM: C[M,N] = A[M,K] @ W[K,N] + bias[N]  (optional ReLU)
// 128x128 block, BK=8, 256 threads, 8x8 per thread.
// M,N multiples of 128; K multiple of 8. All row-major.
// ---------------------------------------------------------------------------
template<int RELU>
__global__ void __launch_bounds__(256) sgemm_bias(
    const float* __restrict__ A, const float* __restrict__ W,
    const float* __restrict__ bias, float* __restrict__ C,
    int M, int N, int K)
{
    __shared__ float As[8][128];
    __shared__ float Ws[8][128];

    const int tid  = threadIdx.x;
    const int brow = blockIdx.y * 128;
    const int bcol = blockIdx.x * 128;

    const int arow = tid >> 1;           // 0..127
    const int acol = (tid & 1) << 2;     // 0 or 4
    const int wrow = tid >> 5;           // 0..7
    const int wcol = (tid & 31) << 2;    // 0..124

    const int tr = (tid >> 4) << 3;      // 0..120
    const int tc = (tid & 15) << 3;      // 0..120

    float acc[8][8];
    #pragma unroll
    for (int i = 0; i < 8; i++)
        #pragma unroll
        for (int j = 0; j < 8; j++) acc[i][j] = 0.f;

    const float* Ap = A + (size_t)(brow + arow) * K + acol;
    const float* Wp = W + (size_t)wrow * N + bcol + wcol;

    for (int k0 = 0; k0 < K; k0 += 8) {
        float4 av = *(const float4*)(Ap + k0);
        As[acol + 0][arow] = av.x;
        As[acol + 1][arow] = av.y;
        As[acol + 2][arow] = av.z;
        As[acol + 3][arow] = av.w;
        *(float4*)&Ws[wrow][wcol] = *(const float4*)(Wp + (size_t)k0 * N);
        __syncthreads();

        #pragma unroll
        for (int k = 0; k < 8; k++) {
            float a[8], b[8];
            *(float4*)&a[0] = *(const float4*)&As[k][tr];
            *(float4*)&a[4] = *(const float4*)&As[k][tr + 4];
            *(float4*)&b[0] = *(const float4*)&Ws[k][tc];
            *(float4*)&b[4] = *(const float4*)&Ws[k][tc + 4];
            #pragma unroll
            for (int i = 0; i < 8; i++)
                #pragma unroll
                for (int j = 0; j < 8; j++)
                    acc[i][j] += a[i] * b[j];
        }
        __syncthreads();
    }

    float bv[8];
    #pragma unroll
    for (int j = 0; j < 8; j++) bv[j] = bias[bcol + tc + j];

    #pragma unroll
    for (int i = 0; i < 8; i++) {
        float* Cp = C + (size_t)(brow + tr + i) * N + bcol + tc;
        #pragma unroll
        for (int j = 0; j < 8; j += 4) {
            float4 o;
            o.x = acc[i][j + 0] + bv[j + 0];
            o.y = acc[i][j + 1] + bv[j + 1];
            o.z = acc[i][j + 2] + bv[j + 2];
            o.w = acc[i][j + 3] + bv[j + 3];
            if (RELU) {
                o.x = fmaxf(o.x, 0.f); o.y = fmaxf(o.y, 0.f);
                o.z = fmaxf(o.z, 0.f); o.w = fmaxf(o.w, 0.f);
            }
            *(float4*)(Cp + j) = o;
        }
    }
}

// ---------------------------------------------------------------------------
// Attention scores: S[bh, i, j] = (1/8) * sum_d Q[b*SQ+i, h*64+d] * K[b*sk+j, h*64+d]
// grid: (SQ/64, sk/64, B*H), 256 threads, 64x64 tile, full K=64.
// If causal and the whole 64x64 tile is above the diagonal, skip (softmax
// masks by index, so the unwritten region is never consumed).
// ---------------------------------------------------------------------------
__global__ void __launch_bounds__(256) attn_scores(
    const float* __restrict__ Q, const float* __restrict__ Kmat,
    float* __restrict__ S, int sk, int causal)
{
    const int bh = blockIdx.z;
    const int b  = bh >> 4;
    const int h  = bh & 15;
    const int q0 = blockIdx.x << 6;
    const int k0 = blockIdx.y << 6;
    if (causal && k0 > q0 + 63) return;

    __shared__ float Qs[64][68];   // [k][r]
    __shared__ float Ks[64][68];   // [k][c]

    const int tid = threadIdx.x;
    const float* Qb = Q    + ((size_t)(b * SQ_ + q0)) * D_ + h * DK_;
    const float* Kb = Kmat + ((size_t)b * sk + k0)    * D_ + h * DK_;

    #pragma unroll
    for (int it = 0; it < 4; it++) {
        int r = (tid >> 4) + (it << 4);   // 0..63
        int c = (tid & 15) << 2;          // 0..60
        float4 qv = *(const float4*)(Qb + (size_t)r * D_ + c);
        Qs[c + 0][r] = qv.x; Qs[c + 1][r] = qv.y;
        Qs[c + 2][r] = qv.z; Qs[c + 3][r] = qv.w;
        float4 kv = *(const float4*)(Kb + (size_t)r * D_ + c);
        Ks[c + 0][r] = kv.x; Ks[c + 1][r] = kv.y;
        Ks[c + 2][r] = kv.z; Ks[c + 3][r] = kv.w;
    }
    __syncthreads();

    const int tr = (tid >> 4) << 2;
    const int tc = (tid & 15) << 2;
    float acc[4][4] = {};
    #pragma unroll
    for (int k = 0; k < 64; k++) {
        float a[4], bb[4];
        *(float4*)a  = *(const float4*)&Qs[k][tr];
        *(float4*)bb = *(const float4*)&Ks[k][tc];
        #pragma unroll
        for (int i = 0; i < 4; i++)
            #pragma unroll
            for (int j = 0; j < 4; j++)
                acc[i][j] += a[i] * bb[j];
    }

    #pragma unroll
    for (int i = 0; i < 4; i++) {
        float4 o;
        o.x = acc[i][0] * 0.125f;
        o.y = acc[i][1] * 0.125f;
        o.z = acc[i][2] * 0.125f;
        o.w = acc[i][3] * 0.125f;
        *(float4*)(S + ((size_t)bh * SQ_ + q0 + tr + i) * sk + k0 + tc) = o;
    }
}

// ---------------------------------------------------------------------------
// PV: ctx[b*SQ+i, h*64+d] = sum_j P[bh, i, j] * V[b*sk+j, h*64+d]
// grid: (SQ/64, 1, B*H), 256 threads, 64x64 tile, BK=32 over sk.
// ---------------------------------------------------------------------------
__global__ void __launch_bounds__(256) attn_pv(
    const float* __restrict__ P, const float* __restrict__ V,
    float* __restrict__ ctx, int sk)
{
    const int bh = blockIdx.z;
    const int b  = bh >> 4;
    const int h  = bh & 15;
    const int q0 = blockIdx.x << 6;

    __shared__ float Ps[32][68];   // [k][r]
    __shared__ float Vs[32][68];   // [k][c]

    const int tid = threadIdx.x;
    const float* Pb = P + ((size_t)bh * SQ_ + q0) * sk;
    const float* Vb = V + ((size_t)b * sk) * D_ + h * DK_;

    const int tr = (tid >> 4) << 2;
    const int tc = (tid & 15) << 2;
    float acc[4][4] = {};

    for (int k0 = 0; k0 < sk; k0 += 32) {
        #pragma unroll
        for (int it = 0; it < 2; it++) {
            int r = (tid >> 3) + (it << 5);    // 0..63
            int c = (tid & 7) << 2;            // 0..28
            float4 p4 = *(const float4*)(Pb + (size_t)r * sk + k0 + c);
            Ps[c + 0][r] = p4.x; Ps[c + 1][r] = p4.y;
            Ps[c + 2][r] = p4.z; Ps[c + 3][r] = p4.w;

            int r2 = (tid >> 4) + (it << 4);   // 0..31
            int c2 = (tid & 15) << 2;          // 0..60
            *(float4*)&Vs[r2][c2] = *(const float4*)(Vb + (size_t)(k0 + r2) * D_ + c2);
        }
        __syncthreads();

        #pragma unroll
        for (int k = 0; k < 32; k++) {
            float a[4], bb[4];
            *(float4*)a  = *(const float4*)&Ps[k][tr];
            *(float4*)bb = *(const float4*)&Vs[k][tc];
            #pragma unroll
            for (int i = 0; i < 4; i++)
                #pragma unroll
                for (int j = 0; j < 4; j++)
                    acc[i][j] += a[i] * bb[j];
        }
        __syncthreads();
    }

    #pragma unroll
    for (int i = 0; i < 4; i++) {
        float4 o = make_float4(acc[i][0], acc[i][1], acc[i][2], acc[i][3]);
        *(float4*)(ctx + ((size_t)(b * SQ_ + q0 + tr + i)) * D_ + h * DK_ + tc) = o;
    }
}

// ---------------------------------------------------------------------------
// Causal softmax in place: rows of length 512, row i valid for j <= (i mod 512).
// 128 threads per row (4 elements each).
// ---------------------------------------------------------------------------
__global__ void softmax_causal_k(float* __restrict__ S)
{
    const int row = blockIdx.x;
    const int i   = row & (SQ_ - 1);
    float* p = S + (size_t)row * SQ_;
    const int tid  = threadIdx.x;
    const int base = tid << 2;

    float4 v4 = *(const float4*)(p + base);
    float v[4] = {v4.x, v4.y, v4.z, v4.w};

    float m = -3.402823e38f;
    #pragma unroll
    for (int j = 0; j < 4; j++) if (base + j <= i) m = fmaxf(m, v[j]);

    __shared__ float sm[4];
    #pragma unroll
    for (int o = 16; o > 0; o >>= 1) m = fmaxf(m, __shfl_xor_sync(0xffffffffu, m, o));
    if ((tid & 31) == 0) sm[tid >> 5] = m;
    __syncthreads();
    m = fmaxf(fmaxf(sm[0], sm[1]), fmaxf(sm[2], sm[3]));

    float s = 0.f;
    #pragma unroll
    for (int j = 0; j < 4; j++) {
        if (base + j <= i) { v[j] = __expf(v[j] - m); s += v[j]; }
        else v[j] = 0.f;
    }
    __shared__ float ss[4];
    #pragma unroll
    for (int o = 16; o > 0; o >>= 1) s += __shfl_xor_sync(0xffffffffu, s, o);
    if ((tid & 31) == 0) ss[tid >> 5] = s;
    __syncthreads();
    s = ss[0] + ss[1] + ss[2] + ss[3];

    const float inv = 1.0f / s;
    v4 = make_float4(v[0] * inv, v[1] * inv, v[2] * inv, v[3] * inv);
    *(float4*)(p + base) = v4;
}

// ---------------------------------------------------------------------------
// Masked softmax in place: rows of length 1024, mask[b, j] == 0 -> prob 0.
// 256 threads per row (4 elements each). b = row / (H*SQ).
// ---------------------------------------------------------------------------
__global__ void softmax_mask_k(float* __restrict__ S, const int* __restrict__ mask)
{
    const int row  = blockIdx.x;
    const int b    = row >> 13;    // / (H_*SQ_) = 8192
    float* p = S + (size_t)row * SK_;
    const int* mrow = mask + b * SK_;
    const int tid  = threadIdx.x;
    const int base = tid << 2;

    float4 v4 = *(const float4*)(p + base);
    int4   m4 = *(const int4*)(mrow + base);
    float v[4] = {v4.x, v4.y, v4.z, v4.w};
    int   mv[4] = {m4.x, m4.y, m4.z, m4.w};

    float m = -3.402823e38f;
    #pragma unroll
    for (int j = 0; j < 4; j++) if (mv[j]) m = fmaxf(m, v[j]);

    __shared__ float sm[8];
    #pragma unroll
    for (int o = 16; o > 0; o >>= 1) m = fmaxf(m, __shfl_xor_sync(0xffffffffu, m, o));
    if ((tid & 31) == 0) sm[tid >> 5] = m;
    __syncthreads();
    #pragma unroll
    for (int w = 0; w < 8; w++) m = fmaxf(m, sm[w]);

    float s = 0.f;
    #pragma unroll
    for (int j = 0; j < 4; j++) {
        if (mv[j]) { v[j] = __expf(v[j] - m); s += v[j]; }
        else v[j] = 0.f;
    }
    __shared__ float ss[8];
    #pragma unroll
    for (int o = 16; o > 0; o >>= 1) s += __shfl_xor_sync(0xffffffffu, s, o);
    if ((tid & 31) == 0) ss[tid >> 5] = s;
    __syncthreads();
    s = 0.f;
    #pragma unroll
    for (int w = 0; w < 8; w++) s += ss[w];

    const float inv = 1.0f / s;
    v4 = make_float4(v[0] * inv, v[1] * inv, v[2] * inv, v[3] * inv);
    *(float4*)(p + base) = v4;
}

// ---------------------------------------------------------------------------
// out[row] = LayerNorm(x[row] + r[row]) * g + b   (rows of D_=1024; 256 threads)
// ---------------------------------------------------------------------------
__global__ void add_ln_k(const float* __restrict__ x, const float* __restrict__ r,
                         const float* __restrict__ g, const float* __restrict__ be,
                         float* __restrict__ out)
{
    const int row  = blockIdx.x;
    const int tid  = threadIdx.x;
    const int base = tid << 2;

    float4 xv = *(const float4*)(x + (size_t)row * D_ + base);
    float4 rv = *(const float4*)(r + (size_t)row * D_ + base);
    float v[4] = {xv.x + rv.x, xv.y + rv.y, xv.z + rv.z, xv.w + rv.w};

    __shared__ float sh1[8], sh2[8];

    float s = v[0] + v[1] + v[2] + v[3];
    #pragma unroll
    for (int o = 16; o > 0; o >>= 1) s += __shfl_xor_sync(0xffffffffu, s, o);
    if ((tid & 31) == 0) sh1[tid >> 5] = s;
    __syncthreads();
    float tot = 0.f;
    #pragma unroll
    for (int w = 0; w < 8; w++) tot += sh1[w];
    const float mu = tot * (1.0f / (float)D_);

    float q = 0.f;
    #pragma unroll
    for (int j = 0; j < 4; j++) { float d = v[j] - mu; q += d * d; }
    #pragma unroll
    for (int o = 16; o > 0; o >>= 1) q += __shfl_xor_sync(0xffffffffu, q, o);
    if ((tid & 31) == 0) sh2[tid >> 5] = q;
    __syncthreads();
    float qtot = 0.f;
    #pragma unroll
    for (int w = 0; w < 8; w++) qtot += sh2[w];
    const float rs = rsqrtf(qtot * (1.0f / (float)D_) + 1e-5f);

    float4 gv = *(const float4*)(g + base);
    float4 bv = *(const float4*)(be + base);
    float4 o;
    o.x = (v[0] - mu) * rs * gv.x + bv.x;
    o.y = (v[1] - mu) * rs * gv.y + bv.y;
    o.z = (v[2] - mu) * rs * gv.z + bv.z;
    o.w = (v[3] - mu) * rs * gv.w + bv.w;
    *(float4*)(out + (size_t)row * D_ + base) = o;
}

// ---------------------------------------------------------------------------
// Launch
// ---------------------------------------------------------------------------
extern "C" void kernel_launch(void* const* d_in, const int* in_sizes, int n_in,
                              void* d_out, int out_size)
{
    (void)in_sizes; (void)n_in; (void)out_size;

    const float* x    = (const float*)d_in[0];
    const float* enc  = (const float*)d_in[1];
    const int*   mask = (const int*)  d_in[2];
    const float *a1_wq = (const float*)d_in[3],  *a1_bq = (const float*)d_in[4];
    const float *a1_wk = (const float*)d_in[5],  *a1_bk = (const float*)d_in[6];
    const float *a1_wv = (const float*)d_in[7],  *a1_bv = (const float*)d_in[8];
    const float *a1_wo = (const float*)d_in[9],  *a1_bo = (const float*)d_in[10];
    const float *a2_wq = (const float*)d_in[11], *a2_bq = (const float*)d_in[12];
    const float *a2_wk = (const float*)d_in[13], *a2_bk = (const float*)d_in[14];
    const float *a2_wv = (const float*)d_in[15], *a2_bv = (const float*)d_in[16];
    const float *a2_wo = (const float*)d_in[17], *a2_bo = (const float*)d_in[18];
    const float *ff_w1 = (const float*)d_in[19], *ff_b1 = (const float*)d_in[20];
    const float *ff_w2 = (const float*)d_in[21], *ff_b2 = (const float*)d_in[22];
    const float *ln1_g = (const float*)d_in[23], *ln1_b = (const float*)d_in[24];
    const float *ln2_g = (const float*)d_in[25], *ln2_b = (const float*)d_in[26];
    const float *ln3_g = (const float*)d_in[27], *ln3_b = (const float*)d_in[28];

    float *q, *k, *v, *ctx, *o, *x1, *s, *h;
    cudaGetSymbolAddress((void**)&q,   g_q);
    cudaGetSymbolAddress((void**)&k,   g_k);
    cudaGetSymbolAddress((void**)&v,   g_v);
    cudaGetSymbolAddress((void**)&ctx, g_ctx);
    cudaGetSymbolAddress((void**)&o,   g_o);
    cudaGetSymbolAddress((void**)&x1,  g_x1);
    cudaGetSymbolAddress((void**)&s,   g_s);
    cudaGetSymbolAddress((void**)&h,   g_h);

    float* out_x    = (float*)d_out;
    float* out_attn = out_x + (size_t)ROWS_Q * D_;   // x first, then attn

    const dim3 blk256(256);
    const dim3 g_proj(D_ / 128, ROWS_Q / 128);       // (8, 32)
    const dim3 g_projK(D_ / 128, ROWS_K / 128);      // (8, 64)
    const dim3 g_ff1(FF_ / 128, ROWS_Q / 128);       // (32, 32)
    const dim3 g_ff2(D_ / 128, ROWS_Q / 128);        // (8, 32)

    // ---- self-attention ----
    sgemm_bias<0><<<g_proj, blk256>>>(x, a1_wq, a1_bq, q, ROWS_Q, D_, D_);
    sgemm_bias<0><<<g_proj, blk256>>>(x, a1_wk, a1_bk, k, ROWS_Q, D_, D_);
    sgemm_bias<0><<<g_proj, blk256>>>(x, a1_wv, a1_bv, v, ROWS_Q, D_, D_);

    attn_scores<<<dim3(SQ_ / 64, SQ_ / 64, B_ * H_), blk256>>>(q, k, s, SQ_, 1);
    softmax_causal_k<<<B_ * H_ * SQ_, 128>>>(s);
    attn_pv<<<dim3(SQ_ / 64, 1, B_ * H_), blk256>>>(s, v, ctx, SQ_);

    sgemm_bias<0><<<g_proj, blk256>>>(ctx, a1_wo, a1_bo, o, ROWS_Q, D_, D_);
    add_ln_k<<<ROWS_Q, blk256>>>(x, o, ln1_g, ln1_b, x1);

    // ---- cross-attention (A goes straight to d_out) ----
    sgemm_bias<0><<<g_proj,  blk256>>>(x1,  a2_wq, a2_bq, q, ROWS_Q, D_, D_);
    sgemm_bias<0><<<g_projK, blk256>>>(enc, a2_wk, a2_bk, k, ROWS_K, D_, D_);
    sgemm_bias<0><<<g_projK, blk256>>>(enc, a2_wv, a2_bv, v, ROWS_K, D_, D_);

    attn_scores<<<dim3(SQ_ / 64, SK_ / 64, B_ * H_), blk256>>>(q, k, out_attn, SK_, 0);
    softmax_mask_k<<<B_ * H_ * SQ_, blk256>>>(out_attn, mask);
    attn_pv<<<dim3(SQ_ / 64, 1, B_ * H_), blk256>>>(out_attn, v, ctx, SK_);

    sgemm_bias<0><<<g_proj, blk256>>>(ctx, a2_wo, a2_bo, o, ROWS_Q, D_, D_);
    add_ln_k<<<ROWS_Q, blk256>>>(x1, o, ln2_g, ln2_b, q);   // q now holds x2

    // ---- feed-forward ----
    sgemm_bias<1><<<g_ff1, blk256>>>(q, ff_w1, ff_b1, h, ROWS_Q, FF_, D_);
    sgemm_bias<0><<<g_ff2, blk256>>>(h, ff_w2, ff_b2, o, ROWS_Q, D_, FF_);
    add_ln_k<<<ROWS_Q, blk256>>>(q, o, ln3_g, ln3_b, out_x);
}